// round 4
// baseline (speedup 1.0000x reference)
#include <cuda_runtime.h>
#include <cuda_bf16.h>
#include <math.h>
#include <stdint.h>

#define NN 100000
#define EE 500000
#define GG 2048
#define DIM 128
#define OUTD 64
#define BN_EPS 1e-5f

// ---------------- scratch (device globals; no allocation allowed) ----------------
__device__ float g_agg[NN * DIM];
__device__ float g_y[NN * DIM];
__device__ float g_h[NN * DIM];
__device__ float g_pool[GG * DIM];
__device__ float g_code[GG * OUTD];
__device__ float g_colsum[DIM];
__device__ float g_colsumsq[DIM];
__device__ float g_scale[DIM];
__device__ float g_shift[DIM];
__device__ int g_src[EE];
__device__ int g_dst[EE];
__device__ int g_batch[NN];
// formatted weights: [matrix][hi/lo][128 pairs * 32 lanes] of uint2
__device__ uint2 g_wfmt[4][2 * 4096];

// ---------------- helpers ----------------
__device__ __forceinline__ uint32_t pack_bf2(float a, float b) {
    __nv_bfloat162 t;
    t.x = __float2bfloat16(a);
    t.y = __float2bfloat16(b);
    return *reinterpret_cast<uint32_t*>(&t);
}
__device__ __forceinline__ void split_bf2(float a, float b, uint32_t& hi, uint32_t& lo) {
    __nv_bfloat16 ha = __float2bfloat16(a);
    __nv_bfloat16 hb = __float2bfloat16(b);
    float ra = a - __bfloat162float(ha);
    float rb = b - __bfloat162float(hb);
    __nv_bfloat162 th;
    th.x = ha; th.y = hb;
    hi = *reinterpret_cast<uint32_t*>(&th);
    lo = pack_bf2(ra, rb);
}
__device__ __forceinline__ void mma16816(float c[4], const uint32_t a[4], uint32_t b0, uint32_t b1) {
    asm volatile(
        "mma.sync.aligned.m16n8k16.row.col.f32.bf16.bf16.f32 "
        "{%0,%1,%2,%3}, {%4,%5,%6,%7}, {%8,%9}, {%0,%1,%2,%3};"
        : "+f"(c[0]), "+f"(c[1]), "+f"(c[2]), "+f"(c[3])
        : "r"(a[0]), "r"(a[1]), "r"(a[2]), "r"(a[3]), "r"(b0), "r"(b1));
}

// ---------------- weight formatter: W[128,128] fp32 -> mma B-frag hi/lo ----------------
// pair p = kstep*16 + ntile; lane holds B[k0..k0+1][n] (reg0) and B[k0+8..k0+9][n] (reg1)
// with k0 = kstep*16 + (lane&3)*2, n = ntile*8 + (lane>>2)
__global__ void format_w(const float* __restrict__ W, uint2* __restrict__ wf) {
    int tid = threadIdx.x;
    int warp = tid >> 5, lane = tid & 31;
    int wglob = blockIdx.x * 8 + warp;  // 0..31
#pragma unroll
    for (int i = 0; i < 4; i++) {
        int p = wglob * 4 + i;  // 0..127
        int kstep = p >> 4, ntile = p & 15;
        int k0 = kstep * 16 + (lane & 3) * 2;
        int n = ntile * 8 + (lane >> 2);
        float w00 = W[k0 * 128 + n];
        float w01 = W[(k0 + 1) * 128 + n];
        float w10 = W[(k0 + 8) * 128 + n];
        float w11 = W[(k0 + 9) * 128 + n];
        uint32_t h0, l0, h1, l1;
        split_bf2(w00, w01, h0, l0);
        split_bf2(w10, w11, h1, l1);
        wf[p * 32 + lane] = make_uint2(h0, h1);
        wf[4096 + p * 32 + lane] = make_uint2(l0, l1);
    }
}

// ---------------- index canonicalization (dtype-robust) ----------------
__device__ __forceinline__ bool is_int64_layout(const int* raw, int n_vals) {
    int nchk = n_vals < 64 ? n_vals : 64;
    for (int i = 0; i < nchk; i++)
        if (raw[2 * i + 1] != 0) return false;
    return true;
}

__global__ void convert_edges(const int* __restrict__ raw, int* __restrict__ src,
                              int* __restrict__ dst) {
    bool w = is_int64_layout(raw, 2 * EE);
    int i = blockIdx.x * blockDim.x + threadIdx.x;
    int stride = gridDim.x * blockDim.x;
    if (w) {
        const long long* r = (const long long*)raw;
        for (int e = i; e < EE; e += stride) {
            src[e] = (int)r[e];
            dst[e] = (int)r[EE + e];
        }
    } else {
        for (int e = i; e < EE; e += stride) {
            src[e] = raw[e];
            dst[e] = raw[EE + e];
        }
    }
}

__global__ void convert_batch(const int* __restrict__ raw, int* __restrict__ out) {
    bool w = is_int64_layout(raw, NN);
    int i = blockIdx.x * blockDim.x + threadIdx.x;
    int stride = gridDim.x * blockDim.x;
    if (w) {
        const long long* r = (const long long*)raw;
        for (int n = i; n < NN; n += stride) out[n] = (int)r[n];
    } else {
        for (int n = i; n < NN; n += stride) out[n] = raw[n];
    }
}

// ---------------- utility kernels ----------------
__global__ void zero_f(float* __restrict__ p, int n) {
    int i = blockIdx.x * blockDim.x + threadIdx.x;
    int stride = gridDim.x * blockDim.x;
    float4* p4 = (float4*)p;
    int n4 = n >> 2;
    for (int k = i; k < n4; k += stride) p4[k] = make_float4(0.f, 0.f, 0.f, 0.f);
}

__global__ void zero_stats(float* __restrict__ a, float* __restrict__ b) {
    int i = threadIdx.x;
    if (i < DIM) { a[i] = 0.f; b[i] = 0.f; }
}

// ---------------- edge aggregation ----------------
__global__ void edge_agg(const float* __restrict__ h, const int* __restrict__ src,
                         const int* __restrict__ dst, float* __restrict__ agg, int E) {
    int t = blockIdx.x * blockDim.x + threadIdx.x;
    int e = t >> 5;
    int lane = t & 31;
    if (e >= E) return;
    int s = src[e];
    int d = dst[e];
    if ((unsigned)s >= NN || (unsigned)d >= NN) return;
    float4 v = ((const float4*)(h + (size_t)s * DIM))[lane];
    float* a = agg + (size_t)d * DIM + lane * 4;
    atomicAdd(a + 0, v.x);
    atomicAdd(a + 1, v.y);
    atomicAdd(a + 2, v.z);
    atomicAdd(a + 3, v.w);
}

// ---------------- pooling ----------------
__global__ void pool_kernel(const float* __restrict__ h, const int* __restrict__ batch,
                            float* __restrict__ pool, int n_nodes) {
    int t = blockIdx.x * blockDim.x + threadIdx.x;
    int n = t >> 5;
    int lane = t & 31;
    if (n >= n_nodes) return;
    int g = batch[n];
    if ((unsigned)g >= GG) return;
    float4 v = ((const float4*)(h + (size_t)n * DIM))[lane];
    float* p = pool + (size_t)g * DIM + lane * 4;
    atomicAdd(p + 0, v.x);
    atomicAdd(p + 1, v.y);
    atomicAdd(p + 2, v.z);
    atomicAdd(p + 3, v.w);
}

// ---------------- BN finalize ----------------
__global__ void bn_finalize(const float* __restrict__ colsum, const float* __restrict__ colsumsq,
                            const float* __restrict__ gamma, const float* __restrict__ beta,
                            float* __restrict__ scale, float* __restrict__ shift, int M) {
    int c = threadIdx.x;
    if (c >= DIM) return;
    float invM = 1.f / (float)M;
    float mean = colsum[c] * invM;
    float var = colsumsq[c] * invM - mean * mean;
    float sc = gamma[c] * rsqrtf(var + BN_EPS);
    scale[c] = sc;
    shift[c] = beta[c] - mean * sc;
}

// ---------------- mma GEMM: C[M,128] = act(A'[M,128] @ W[128,128] + b) ----------------
// bf16 hi/lo 3-pass. IN_MODE 1: A' = A0 + A1 ; 2: A' = relu(scale*A0 + shift)
// 8 warps; warp w computes rows [w*16, w*16+16) x all 128 cols.
// STATS: accumulate column sum/sumsq of the produced (pre-activation) y.
#define OFF_AS 0
#define AS_STRIDE 136
#define OFF_WF (128 * AS_STRIDE * 4)              // 69632
#define OFF_BIAS (OFF_WF + 65536)                 // 135168
#define OFF_SCALE (OFF_BIAS + 512)
#define OFF_SHIFT (OFF_SCALE + 512)
#define MMA_SMEM (OFF_SHIFT + 512)                // 136704

template <int IN_MODE, bool OUT_RELU, bool STATS>
__global__ __launch_bounds__(256, 1) void gemm_mma(
    const float* __restrict__ A0, const float* __restrict__ A1,
    const float* __restrict__ scale, const float* __restrict__ shift,
    const uint2* __restrict__ wfmt, const float* __restrict__ bias,
    float* __restrict__ C, int M,
    float* __restrict__ colsum, float* __restrict__ colsumsq) {
    extern __shared__ char smc[];
    float* As = (float*)(smc + OFF_AS);
    uint2* Wf = (uint2*)(smc + OFF_WF);
    float* sb = (float*)(smc + OFF_BIAS);
    float* ssc = (float*)(smc + OFF_SCALE);
    float* ssh = (float*)(smc + OFF_SHIFT);
    int tid = threadIdx.x;
    int row0 = blockIdx.x * 128;

    // stage formatted W (8192 uint2 = 4096 uint4)
    {
        const uint4* srcv = (const uint4*)wfmt;
        uint4* dstv = (uint4*)Wf;
#pragma unroll
        for (int i = 0; i < 16; i++) dstv[tid + i * 256] = srcv[tid + i * 256];
    }
    if (tid < 32) ((float4*)sb)[tid] = ((const float4*)bias)[tid];
    if (IN_MODE == 2) {
        if (tid >= 32 && tid < 64) ((float4*)ssc)[tid - 32] = ((const float4*)scale)[tid - 32];
        if (tid >= 64 && tid < 96) ((float4*)ssh)[tid - 64] = ((const float4*)shift)[tid - 64];
    }
    // stage A tile (with input transform), fp32, padded stride 136
    {
#pragma unroll
        for (int i = 0; i < 16; i++) {
            int idx4 = tid + i * 256;  // 4096 float4
            int row = idx4 >> 5, c4 = idx4 & 31;
            int gr = row0 + row;
            float4 v = make_float4(0.f, 0.f, 0.f, 0.f);
            if (gr < M) {
                v = ((const float4*)A0)[(size_t)gr * 32 + c4];
                if (IN_MODE == 1) {
                    float4 u = ((const float4*)A1)[(size_t)gr * 32 + c4];
                    v.x += u.x; v.y += u.y; v.z += u.z; v.w += u.w;
                } else if (IN_MODE == 2) {
                    const float4 sc = ((const float4*)scale)[c4];
                    const float4 sh = ((const float4*)shift)[c4];
                    v.x = fmaxf(v.x * sc.x + sh.x, 0.f);
                    v.y = fmaxf(v.y * sc.y + sh.y, 0.f);
                    v.z = fmaxf(v.z * sc.z + sh.z, 0.f);
                    v.w = fmaxf(v.w * sc.w + sh.w, 0.f);
                }
            }
            *(float4*)(As + row * AS_STRIDE + c4 * 4) = v;
        }
    }
    __syncthreads();

    int warp = tid >> 5, lane = tid & 31;
    int r_lo = warp * 16 + (lane >> 2);
    const uint2* WfHi = Wf;
    const uint2* WfLo = Wf + 4096;

    float c[16][4];
#pragma unroll
    for (int i = 0; i < 16; i++)
#pragma unroll
        for (int j = 0; j < 4; j++) c[i][j] = 0.f;

#pragma unroll
    for (int kstep = 0; kstep < 8; kstep++) {
        int cb = (lane & 3) * 2 + kstep * 16;
        float2 f0 = *(const float2*)(As + r_lo * AS_STRIDE + cb);
        float2 f1 = *(const float2*)(As + (r_lo + 8) * AS_STRIDE + cb);
        float2 f2 = *(const float2*)(As + r_lo * AS_STRIDE + cb + 8);
        float2 f3 = *(const float2*)(As + (r_lo + 8) * AS_STRIDE + cb + 8);
        uint32_t ah[4], al[4];
        split_bf2(f0.x, f0.y, ah[0], al[0]);
        split_bf2(f1.x, f1.y, ah[1], al[1]);
        split_bf2(f2.x, f2.y, ah[2], al[2]);
        split_bf2(f3.x, f3.y, ah[3], al[3]);
#pragma unroll
        for (int ntile = 0; ntile < 16; ntile++) {
            uint2 bh = WfHi[(kstep * 16 + ntile) * 32 + lane];
            uint2 bl = WfLo[(kstep * 16 + ntile) * 32 + lane];
            mma16816(c[ntile], ah, bh.x, bh.y);
            mma16816(c[ntile], al, bh.x, bh.y);
            mma16816(c[ntile], ah, bl.x, bl.y);
        }
    }

    // epilogue
    int gr0 = row0 + warp * 16 + (lane >> 2);
    int gr1 = gr0 + 8;
    bool v0 = gr0 < M, v1 = gr1 < M;
#pragma unroll
    for (int ntile = 0; ntile < 16; ntile++) {
        int col0 = ntile * 8 + (lane & 3) * 2;
        float y0 = c[ntile][0] + sb[col0];
        float y1 = c[ntile][1] + sb[col0 + 1];
        float y2 = c[ntile][2] + sb[col0];
        float y3 = c[ntile][3] + sb[col0 + 1];
        float o0 = y0, o1 = y1, o2 = y2, o3 = y3;
        if (OUT_RELU) {
            o0 = fmaxf(o0, 0.f); o1 = fmaxf(o1, 0.f);
            o2 = fmaxf(o2, 0.f); o3 = fmaxf(o3, 0.f);
        }
        if (v0) *(float2*)(C + (size_t)gr0 * 128 + col0) = make_float2(o0, o1);
        if (v1) *(float2*)(C + (size_t)gr1 * 128 + col0) = make_float2(o2, o3);
        if (STATS) {
            float s0 = (v0 ? y0 : 0.f) + (v1 ? y2 : 0.f);
            float s1 = (v0 ? y1 : 0.f) + (v1 ? y3 : 0.f);
            float q0 = (v0 ? y0 * y0 : 0.f) + (v1 ? y2 * y2 : 0.f);
            float q1 = (v0 ? y1 * y1 : 0.f) + (v1 ? y3 * y3 : 0.f);
#pragma unroll
            for (int off = 4; off < 32; off <<= 1) {
                s0 += __shfl_xor_sync(0xffffffffu, s0, off);
                s1 += __shfl_xor_sync(0xffffffffu, s1, off);
                q0 += __shfl_xor_sync(0xffffffffu, q0, off);
                q1 += __shfl_xor_sync(0xffffffffu, q1, off);
            }
            if (lane < 4) {
                atomicAdd(&colsum[col0], s0);
                atomicAdd(&colsum[col0 + 1], s1);
                atomicAdd(&colsumsq[col0], q0);
                atomicAdd(&colsumsq[col0 + 1], q1);
            }
        }
    }
}

// ---------------- code MLP branch ----------------
__global__ void code_mlp(const float* __restrict__ code_x,
                         const float* __restrict__ w1, const float* __restrict__ b1,
                         const float* __restrict__ w2, const float* __restrict__ b2,
                         const float* __restrict__ w3, const float* __restrict__ b3,
                         float* __restrict__ code_out) {
    __shared__ float buf0[128], buf1[128];
    __shared__ float red[64];
    __shared__ float s_mx, s_lse;
    int g = blockIdx.x, j = threadIdx.x;
    buf0[j] = code_x[(size_t)g * 128 + j];
    __syncthreads();
    float acc = b1[j];
    for (int k = 0; k < 128; k++) acc += buf0[k] * w1[k * 128 + j];
    buf1[j] = fmaxf(acc, 0.f);
    __syncthreads();
    float acc2 = b2[j];
    for (int k = 0; k < 128; k++) acc2 += buf1[k] * w2[k * 128 + j];
    buf0[j] = fmaxf(acc2, 0.f);
    __syncthreads();
    float v = 0.f;
    if (j < 64) {
        v = b3[j];
        for (int k = 0; k < 128; k++) v += buf0[k] * w3[k * 64 + j];
        red[j] = v;
    }
    __syncthreads();
    if (j == 0) {
        float m = red[0];
        for (int i = 1; i < 64; i++) m = fmaxf(m, red[i]);
        float s = 0.f;
        for (int i = 0; i < 64; i++) s += expf(red[i] - m);
        s_mx = m;
        s_lse = logf(s);
    }
    __syncthreads();
    if (j < 64) code_out[(size_t)g * 64 + j] = v - s_mx - s_lse;
}

// ---------------- head ----------------
__global__ void head_kernel(const float* __restrict__ pool,
                            const float* __restrict__ l1w, const float* __restrict__ l1b,
                            const float* __restrict__ l2w, const float* __restrict__ l2b,
                            const float* __restrict__ code,
                            const float* __restrict__ finw, const float* __restrict__ finb,
                            float* __restrict__ out) {
    __shared__ float p[128], t[128], cc[128];
    __shared__ float r0[128], r1[128];
    int g = blockIdx.x, j = threadIdx.x;
    p[j] = pool[(size_t)g * 128 + j];
    __syncthreads();
    float a = l1b[j];
    for (int k = 0; k < 128; k++) a += p[k] * l1w[k * 128 + j];
    t[j] = fmaxf(a, 0.f);
    __syncthreads();
    if (j < 64) {
        float v = l2b[j];
        for (int k = 0; k < 128; k++) v += t[k] * l2w[k * 64 + j];
        cc[64 + j] = v;
        cc[j] = code[(size_t)g * 64 + j];
    }
    __syncthreads();
    r0[j] = cc[j] * finw[j * 2 + 0];
    r1[j] = cc[j] * finw[j * 2 + 1];
    __syncthreads();
    if (j == 0) {
        float o0 = finb[0], o1 = finb[1];
        for (int k = 0; k < 128; k++) { o0 += r0[k]; o1 += r1[k]; }
        float m = fmaxf(o0, o1);
        float l = m + logf(expf(o0 - m) + expf(o1 - m));
        out[(size_t)g * 2 + 0] = o0 - l;
        out[(size_t)g * 2 + 1] = o1 - l;
    }
}

// ---------------- launcher ----------------
extern "C" void kernel_launch(void* const* d_in, const int* in_sizes, int n_in,
                              void* d_out, int out_size) {
    const float* x = (const float*)d_in[0];
    const int* ei_raw = (const int*)d_in[1];
    const int* batch_raw = (const int*)d_in[2];
    const float* code_x = (const float*)d_in[3];
    const float* c1_w1 = (const float*)d_in[4];
    const float* c1_b1 = (const float*)d_in[5];
    const float* c1_g = (const float*)d_in[6];
    const float* c1_be = (const float*)d_in[7];
    const float* c1_w2 = (const float*)d_in[8];
    const float* c1_b2 = (const float*)d_in[9];
    const float* c2_w1 = (const float*)d_in[10];
    const float* c2_b1 = (const float*)d_in[11];
    const float* c2_g = (const float*)d_in[12];
    const float* c2_be = (const float*)d_in[13];
    const float* c2_w2 = (const float*)d_in[14];
    const float* c2_b2 = (const float*)d_in[15];
    const float* gl1_w = (const float*)d_in[16];
    const float* gl1_b = (const float*)d_in[17];
    const float* gl2_w = (const float*)d_in[18];
    const float* gl2_b = (const float*)d_in[19];
    const float* fc1_w = (const float*)d_in[20];
    const float* fc1_b = (const float*)d_in[21];
    const float* fc2_w = (const float*)d_in[22];
    const float* fc2_b = (const float*)d_in[23];
    const float* fc3_w = (const float*)d_in[24];
    const float* fc3_b = (const float*)d_in[25];
    const float* fin_w = (const float*)d_in[26];
    const float* fin_b = (const float*)d_in[27];
    float* out = (float*)d_out;

    float *agg, *y, *h, *pool, *code, *colsum, *colsumsq, *scale, *shift;
    int *srcp, *dstp, *batchp;
    uint2* wfmt;
    cudaGetSymbolAddress((void**)&agg, g_agg);
    cudaGetSymbolAddress((void**)&y, g_y);
    cudaGetSymbolAddress((void**)&h, g_h);
    cudaGetSymbolAddress((void**)&pool, g_pool);
    cudaGetSymbolAddress((void**)&code, g_code);
    cudaGetSymbolAddress((void**)&colsum, g_colsum);
    cudaGetSymbolAddress((void**)&colsumsq, g_colsumsq);
    cudaGetSymbolAddress((void**)&scale, g_scale);
    cudaGetSymbolAddress((void**)&shift, g_shift);
    cudaGetSymbolAddress((void**)&srcp, g_src);
    cudaGetSymbolAddress((void**)&dstp, g_dst);
    cudaGetSymbolAddress((void**)&batchp, g_batch);
    cudaGetSymbolAddress((void**)&wfmt, g_wfmt);

    cudaFuncSetAttribute(gemm_mma<1, false, true>, cudaFuncAttributeMaxDynamicSharedMemorySize, MMA_SMEM);
    cudaFuncSetAttribute(gemm_mma<2, true, false>, cudaFuncAttributeMaxDynamicSharedMemorySize, MMA_SMEM);

    const int tc_blocks = (NN + 127) / 128;           // 782
    const int edge_blocks = (EE * 32 + 255) / 256;    // 62500
    const int pool_blocks = (NN * 32 + 255) / 256;    // 12500

    // canonicalize indices + format weights (graph-safe, deterministic)
    convert_edges<<<512, 256>>>(ei_raw, srcp, dstp);
    convert_batch<<<256, 256>>>(batch_raw, batchp);
    format_w<<<4, 256>>>(c1_w1, wfmt + 0 * 8192);
    format_w<<<4, 256>>>(c1_w2, wfmt + 1 * 8192);
    format_w<<<4, 256>>>(c2_w1, wfmt + 2 * 8192);
    format_w<<<4, 256>>>(c2_w2, wfmt + 3 * 8192);

    code_mlp<<<GG, 128>>>(code_x, fc1_w, fc1_b, fc2_w, fc2_b, fc3_w, fc3_b, code);

    zero_f<<<4096, 256>>>(agg, NN * DIM);
    zero_f<<<64, 256>>>(pool, GG * DIM);

    // ---- conv1 ----
    edge_agg<<<edge_blocks, 256>>>(x, srcp, dstp, agg, EE);
    zero_stats<<<1, 128>>>(colsum, colsumsq);
    gemm_mma<1, false, true><<<tc_blocks, 256, MMA_SMEM>>>(
        x, agg, nullptr, nullptr, wfmt + 0 * 8192, c1_b1, y, NN, colsum, colsumsq);
    bn_finalize<<<1, 128>>>(colsum, colsumsq, c1_g, c1_be, scale, shift, NN);
    gemm_mma<2, true, false><<<tc_blocks, 256, MMA_SMEM>>>(
        y, nullptr, scale, shift, wfmt + 1 * 8192, c1_b2, h, NN, nullptr, nullptr);

    // ---- conv2 ----
    zero_f<<<4096, 256>>>(agg, NN * DIM);
    edge_agg<<<edge_blocks, 256>>>(h, srcp, dstp, agg, EE);
    zero_stats<<<1, 128>>>(colsum, colsumsq);
    gemm_mma<1, false, true><<<tc_blocks, 256, MMA_SMEM>>>(
        h, agg, nullptr, nullptr, wfmt + 2 * 8192, c2_b1, y, NN, colsum, colsumsq);
    bn_finalize<<<1, 128>>>(colsum, colsumsq, c2_g, c2_be, scale, shift, NN);
    gemm_mma<2, true, false><<<tc_blocks, 256, MMA_SMEM>>>(
        y, nullptr, scale, shift, wfmt + 3 * 8192, c2_b2, h, NN, nullptr, nullptr);

    // ---- pool + heads ----
    pool_kernel<<<pool_blocks, 256>>>(h, batchp, pool, NN);
    head_kernel<<<GG, 128>>>(pool, gl1_w, gl1_b, gl2_w, gl2_b, code, fin_w, fin_b, out);
}